// round 15
// baseline (speedup 1.0000x reference)
#include <cuda_runtime.h>
#include <cuda_fp16.h>
#include <cstdint>
#include <math.h>

// Problem constants
#define NTOK   4096
#define CDIM   1024
#define EDIM   8
#define FDIM   1024
#define FSDIM  2048
#define NPAIR  8192
#define NPCTA  148        // 1 CTA/SM (256x128 tile, 128 accum regs/thread)

// ---------------- scratch ----------------
__device__ __half g_xh[NTOK * CDIM];
__device__ __half g_w1h[EDIM * FDIM * CDIM];
__device__ __half g_w2h[EDIM * CDIM * FDIM];
__device__ __half g_ws1h[FSDIM * CDIM];
__device__ __half g_ws2h[CDIM * FSDIM];
__device__ __half g_midmoe[NPAIR * FDIM];
__device__ __half g_midsh[NTOK * FSDIM];
__device__ float  g_bin[NPAIR * CDIM];
__device__ int    g_counts[EDIM];
__device__ int    g_fill[EDIM];
__device__ int    g_off[EDIM];
__device__ int    g_te_off[EDIM + 1];   // 256-row-block tile prefix per expert
__device__ int    g_tok_e[NPAIR];
__device__ float  g_tok_w[NPAIR];
__device__ int    g_bin_tok[NPAIR];
__device__ int    g_tok_row[NPAIR];
__device__ int    g_ctr1, g_ctr2;

// ---------------- helpers ----------------
__device__ __forceinline__ uint32_t smem_u32(const void* p) {
    uint32_t a;
    asm("{ .reg .u64 t; cvta.to.shared.u64 t, %1; cvt.u32.u64 %0, t; }" : "=r"(a) : "l"(p));
    return a;
}
__device__ __forceinline__ void cp_async16(uint32_t dst, const void* src) {
    asm volatile("cp.async.ca.shared.global [%0], [%1], 16;" :: "r"(dst), "l"(src));
}
#define CP_COMMIT()   asm volatile("cp.async.commit_group;" ::: "memory")
#define CP_WAIT_1()   asm volatile("cp.async.wait_group 1;" ::: "memory")
#define CP_WAIT_ALL() asm volatile("cp.async.wait_group 0;" ::: "memory")

__device__ __forceinline__ void mma_f16(float* c, const uint32_t* a, const uint32_t* b) {
    asm volatile(
        "mma.sync.aligned.m16n8k16.row.col.f32.f16.f16.f32 "
        "{%0,%1,%2,%3}, {%4,%5,%6,%7}, {%8,%9}, {%0,%1,%2,%3};"
        : "+f"(c[0]), "+f"(c[1]), "+f"(c[2]), "+f"(c[3])
        : "r"(a[0]), "r"(a[1]), "r"(a[2]), "r"(a[3]), "r"(b[0]), "r"(b[1]));
}
__device__ __forceinline__ float sqrelu(float v) { return v > 0.f ? v * v : 0.f; }

// ---------------- GEMM tile core: BM=256, BN=128, BK=64 halfs, 3-stage cp.async ----------------
// SMEM stage: A [ks4][m16x16][reg4][lane32] = 8192 w; B [ks4][n8x16][reg2][lane32] = 4096 w
#define STW 12288
#define BW  8192
#define SMEM_BYTES (3 * STW * 4)    // 144 KB

// 8 warps: wm = wid>>1 (m-quadrant of 64), wn = wid&1 (n-half of 64). acc[4][8][4] = 128 regs.
__device__ __forceinline__ void run_tile(
    const __half* (&pa)[8], const __half* (&pb)[4], int nK,
    uint32_t* smw, uint32_t sm0, int tid, int wm, int wn, int lane,
    float (&acc)[4][8][4])
{
    uint32_t aoff[8], boff[4];
    #pragma unroll
    for (int j = 0; j < 8; j++) {
        int c = tid + j * 256;            // 0..2047: row = c>>3 (0..255), octet o = c&7
        int row = c >> 3, o = c & 7;
        int ks = o >> 1, ch = o & 1;
        aoff[j] = (uint32_t)(((ks * 16 + (row >> 4)) * 4 + (((row >> 3) & 1) + 2 * ch)) * 32 + (row & 7) * 4) * 4u;
    }
    #pragma unroll
    for (int j = 0; j < 4; j++) {
        int c = tid + j * 256;            // 0..1023: row = c>>3 (0..127), octet o = c&7
        int row = c >> 3, o = c & 7;
        int ks = o >> 1, ch = o & 1;
        boff[j] = (uint32_t)(((ks * 16 + (row >> 3)) * 2 + ch) * 32 + (row & 7) * 4) * 4u;
    }

    auto issue = [&](int kt) {
        if (kt < nK) {
            const uint32_t sb = sm0 + (kt % 3) * (STW * 4);
            const int kadv = kt * 64;
            #pragma unroll
            for (int j = 0; j < 8; j++) cp_async16(sb + aoff[j], pa[j] + kadv);
            #pragma unroll
            for (int j = 0; j < 4; j++) cp_async16(sb + BW * 4 + boff[j], pb[j] + kadv);
        }
        CP_COMMIT();
    };

    issue(0); issue(1);

    for (int kt = 0; kt < nK; kt++) {
        CP_WAIT_1();
        __syncthreads();
        issue(kt + 2);
        const uint32_t sb = (kt % 3) * STW;
        #pragma unroll
        for (int s = 0; s < 4; s++) {
            uint32_t bf[8][2];
            #pragma unroll
            for (int j = 0; j < 8; j++) {
                uint32_t off = (uint32_t)(((s * 16 + wn * 8 + j) * 2) * 32 + lane);
                bf[j][0] = smw[sb + BW + off];  bf[j][1] = smw[sb + BW + off + 32];
            }
            #pragma unroll
            for (int i = 0; i < 4; i++) {
                uint32_t a[4];
                uint32_t off = (uint32_t)(((s * 16 + wm * 4 + i) * 4) * 32 + lane);
                #pragma unroll
                for (int r = 0; r < 4; r++) a[r] = smw[sb + off + r * 32];
                #pragma unroll
                for (int j = 0; j < 8; j++) mma_f16(acc[i][j], a, bf[j]);
            }
        }
    }
}

// ---------------- conversions ----------------
__global__ void cvt_weights_kernel(const float* __restrict__ w1, const float* __restrict__ w2,
                                   const float* __restrict__ ws1, const float* __restrict__ ws2) {
    const int WE = EDIM * FDIM * CDIM;
    const int SE = FSDIM * CDIM;
    long long i = (long long)(blockIdx.x * blockDim.x + threadIdx.x) * 4;
    const float* src; __half* dst; long long off;
    if      (i < WE)               { src = w1;  dst = g_w1h;  off = i; }
    else if (i < 2LL * WE)         { src = w2;  dst = g_w2h;  off = i - WE; }
    else if (i < 2LL * WE + SE)    { src = ws1; dst = g_ws1h; off = i - 2LL * WE; }
    else if (i < 2LL * WE + 2*SE)  { src = ws2; dst = g_ws2h; off = i - 2LL * WE - SE; }
    else return;
    float4 v = *(const float4*)(src + off);
    ushort4 hh;
    hh.x = __half_as_ushort(__float2half_rn(v.x));
    hh.y = __half_as_ushort(__float2half_rn(v.y));
    hh.z = __half_as_ushort(__float2half_rn(v.z));
    hh.w = __half_as_ushort(__float2half_rn(v.w));
    *(ushort4*)(dst + off) = hh;
}

// ---------------- routing ----------------
__global__ void init_kernel() {
    int i = threadIdx.x;
    if (i < EDIM) { g_counts[i] = 0; g_fill[i] = 0; }
    if (i == 0) { g_ctr1 = 0; g_ctr2 = 0; }
}

__global__ void router_kernel(const float* __restrict__ x, const float* __restrict__ wr) {
    int gw = (blockIdx.x * blockDim.x + threadIdx.x) >> 5;
    int lane = threadIdx.x & 31;
    if (gw >= NTOK) return;
    const float* xr = x + (size_t)gw * CDIM;
    __half* xhr = g_xh + (size_t)gw * CDIM;
    float acc[EDIM] = {0.f, 0.f, 0.f, 0.f, 0.f, 0.f, 0.f, 0.f};
    for (int c = lane; c < CDIM; c += 32) {
        float xv = xr[c];
        xhr[c] = __float2half_rn(xv);
        #pragma unroll
        for (int e = 0; e < EDIM; e++) acc[e] = fmaf(xv, wr[e * CDIM + c], acc[e]);
    }
    #pragma unroll
    for (int e = 0; e < EDIM; e++) {
        #pragma unroll
        for (int o = 16; o; o >>= 1) acc[e] += __shfl_xor_sync(0xffffffffu, acc[e], o);
    }
    if (lane == 0) {
        float m = acc[0];
        #pragma unroll
        for (int e = 1; e < EDIM; e++) m = fmaxf(m, acc[e]);
        float p[EDIM];
        #pragma unroll
        for (int e = 0; e < EDIM; e++) p[e] = expf(acc[e] - m);
        int i0 = 0; float p0 = p[0];
        #pragma unroll
        for (int e = 1; e < EDIM; e++) if (p[e] > p0) { p0 = p[e]; i0 = e; }
        int i1 = -1; float p1 = -1.f;
        #pragma unroll
        for (int e = 0; e < EDIM; e++) if (e != i0 && p[e] > p1) { p1 = p[e]; i1 = e; }
        float s = p0 + p1;
        g_tok_e[2 * gw + 0] = i0;  g_tok_w[2 * gw + 0] = p0 / s;
        g_tok_e[2 * gw + 1] = i1;  g_tok_w[2 * gw + 1] = p1 / s;
        atomicAdd(&g_counts[i0], 1);
        atomicAdd(&g_counts[i1], 1);
    }
}

// assign: each thread computes the 8-element offset prefix locally (offsets_kernel deleted);
// thread 0 publishes g_off / g_te_off for the GEMM kernels (they launch strictly after).
__global__ void assign_kernel() {
    int t = blockIdx.x * blockDim.x + threadIdx.x;
    if (t >= NTOK) return;
    int cnt[EDIM], off[EDIM];
    int s = 0;
    #pragma unroll
    for (int e = 0; e < EDIM; e++) { cnt[e] = g_counts[e]; off[e] = s; s += cnt[e]; }
    if (t == 0) {
        int ts = 0;
        g_te_off[0] = 0;
        #pragma unroll
        for (int e = 0; e < EDIM; e++) {
            g_off[e] = off[e];
            ts += ((cnt[e] + 255) >> 8) * 8;
            g_te_off[e + 1] = ts;
        }
    }
    #pragma unroll
    for (int k = 0; k < 2; k++) {
        int e = g_tok_e[2 * t + k];
        int slot = atomicAdd(&g_fill[e], 1);
        int r = off[e] + slot;
        g_bin_tok[r] = t;
        g_tok_row[2 * t + k] = r;
    }
}

// ---------------- GEMM1 persistent: tiles [0,256) s1 (16m x 16n), rest moe1 ----------------
__global__ __launch_bounds__(256, 1) void gemm1_persist() {
    extern __shared__ uint32_t smw[];
    const uint32_t sm0 = smem_u32(smw);
    __shared__ int s_t;
    const int tid = threadIdx.x, wid = tid >> 5, lane = tid & 31;
    const int wm = wid >> 1, wn = wid & 1;
    const int total = 256 + g_te_off[EDIM];

    for (;;) {
        __syncthreads();
        if (tid == 0) s_t = atomicAdd(&g_ctr1, 1);
        __syncthreads();
        const int t = s_t;
        if (t >= total) { CP_WAIT_ALL(); break; }

        int m0, n0, Mtot, rowbase, N;
        bool moe;
        const __half* Bp; __half* Out;
        if (t < 256) {
            moe = false; n0 = (t & 15) * 128; m0 = (t >> 4) * 256;
            Mtot = NTOK; rowbase = 0; N = FSDIM; Bp = g_ws1h; Out = g_midsh;
        } else {
            moe = true;
            int tt = t - 256, e = 0;
            while (e < EDIM - 1 && tt >= g_te_off[e + 1]) e++;
            int local = tt - g_te_off[e];
            n0 = (local & 7) * 128; m0 = (local >> 3) * 256;
            Mtot = g_counts[e]; rowbase = g_off[e]; N = FDIM;
            Bp = g_w1h + (size_t)e * FDIM * CDIM; Out = g_midmoe;
        }

        const __half* pa[8]; const __half* pb[4];
        #pragma unroll
        for (int j = 0; j < 8; j++) {
            int c = tid + j * 256;
            int row = c >> 3, o = c & 7;
            int am = m0 + row;
            size_t arow;
            if (moe) arow = (size_t)g_bin_tok[rowbase + (am < Mtot ? am : 0)];
            else     arow = (size_t)(am < Mtot ? am : m0);
            pa[j] = g_xh + arow * CDIM + o * 8;
        }
        #pragma unroll
        for (int j = 0; j < 4; j++) {
            int c = tid + j * 256;
            int row = c >> 3, o = c & 7;
            pb[j] = Bp + (size_t)(n0 + row) * CDIM + o * 8;
        }

        float acc[4][8][4];
        #pragma unroll
        for (int i = 0; i < 4; i++)
            #pragma unroll
            for (int j = 0; j < 8; j++)
                #pragma unroll
                for (int r = 0; r < 4; r++) acc[i][j][r] = 0.f;

        run_tile(pa, pb, CDIM / 64, smw, sm0, tid, wm, wn, lane, acc);

        #pragma unroll
        for (int i = 0; i < 4; i++) {
            const int rbase = m0 + wm * 64 + i * 16 + (lane >> 2);
            #pragma unroll
            for (int half = 0; half < 2; half++) {
                const int mrow = rbase + half * 8;
                if (mrow >= Mtot) continue;
                #pragma unroll
                for (int j = 0; j < 8; j++) {
                    const int col = n0 + wn * 64 + j * 8 + (lane & 3) * 2;
                    __half2 h2 = __floats2half2_rn(sqrelu(acc[i][j][half * 2 + 0]),
                                                   sqrelu(acc[i][j][half * 2 + 1]));
                    *(__half2*)(Out + (size_t)(rowbase + mrow) * N + col) = h2;
                }
            }
        }
    }
}

// ---------------- GEMM2 persistent: tiles [0,128) s2 (16m x 8n), rest moe2 -> bin ----------------
__global__ __launch_bounds__(256, 1) void gemm2_persist(float* __restrict__ OutF) {
    extern __shared__ uint32_t smw[];
    const uint32_t sm0 = smem_u32(smw);
    __shared__ int s_t;
    const int tid = threadIdx.x, wid = tid >> 5, lane = tid & 31;
    const int wm = wid >> 1, wn = wid & 1;
    const int total = 128 + g_te_off[EDIM];

    for (;;) {
        __syncthreads();
        if (tid == 0) s_t = atomicAdd(&g_ctr2, 1);
        __syncthreads();
        const int t = s_t;
        if (t >= total) { CP_WAIT_ALL(); break; }

        int m0, n0, Mtot, rowbase, Kd;
        const __half* Ap; const __half* Bp; float* dst;
        if (t < 128) {
            n0 = (t & 7) * 128; m0 = (t >> 3) * 256;
            Mtot = NTOK; rowbase = 0; Kd = FSDIM;
            Ap = g_midsh; Bp = g_ws2h; dst = OutF;
        } else {
            int tt = t - 128, e = 0;
            while (e < EDIM - 1 && tt >= g_te_off[e + 1]) e++;
            int local = tt - g_te_off[e];
            n0 = (local & 7) * 128; m0 = (local >> 3) * 256;
            Mtot = g_counts[e]; rowbase = g_off[e]; Kd = FDIM;
            Ap = g_midmoe; Bp = g_w2h + (size_t)e * CDIM * FDIM; dst = g_bin;
        }

        const __half* pa[8]; const __half* pb[4];
        #pragma unroll
        for (int j = 0; j < 8; j++) {
            int c = tid + j * 256;
            int row = c >> 3, o = c & 7;
            int am = m0 + row;
            size_t arow = (size_t)(rowbase + (am < Mtot ? am : m0));
            pa[j] = Ap + arow * Kd + o * 8;
        }
        #pragma unroll
        for (int j = 0; j < 4; j++) {
            int c = tid + j * 256;
            int row = c >> 3, o = c & 7;
            pb[j] = Bp + (size_t)(n0 + row) * Kd + o * 8;
        }

        float acc[4][8][4];
        #pragma unroll
        for (int i = 0; i < 4; i++)
            #pragma unroll
            for (int j = 0; j < 8; j++)
                #pragma unroll
                for (int r = 0; r < 4; r++) acc[i][j][r] = 0.f;

        run_tile(pa, pb, Kd / 64, smw, sm0, tid, wm, wn, lane, acc);

        #pragma unroll
        for (int i = 0; i < 4; i++) {
            const int rbase = m0 + wm * 64 + i * 16 + (lane >> 2);
            #pragma unroll
            for (int half = 0; half < 2; half++) {
                const int mrow = rbase + half * 8;
                if (mrow >= Mtot) continue;
                #pragma unroll
                for (int j = 0; j < 8; j++) {
                    const int col = n0 + wn * 64 + j * 8 + (lane & 3) * 2;
                    float2 o2;
                    o2.x = acc[i][j][half * 2 + 0];
                    o2.y = acc[i][j][half * 2 + 1];
                    *(float2*)(dst + (size_t)(rowbase + mrow) * CDIM + col) = o2;
                }
            }
        }
    }
}

// ---------------- combine: out[t] += w0*bin[r0] + w1*bin[r1] ----------------
__global__ void combine_kernel(float* __restrict__ out) {
    int idx = (blockIdx.x * blockDim.x + threadIdx.x) * 4;
    if (idx >= NTOK * CDIM) return;
    int t = idx >> 10;
    int c = idx & 1023;
    float w0 = g_tok_w[2 * t], w1 = g_tok_w[2 * t + 1];
    size_t r0 = (size_t)g_tok_row[2 * t], r1 = (size_t)g_tok_row[2 * t + 1];
    float4 o  = *(float4*)(out + idx);
    float4 b0 = *(const float4*)(g_bin + r0 * CDIM + c);
    float4 b1 = *(const float4*)(g_bin + r1 * CDIM + c);
    o.x += w0 * b0.x + w1 * b1.x;
    o.y += w0 * b0.y + w1 * b1.y;
    o.z += w0 * b0.z + w1 * b1.z;
    o.w += w0 * b0.w + w1 * b1.w;
    *(float4*)(out + idx) = o;
}

// ---------------- launch ----------------
extern "C" void kernel_launch(void* const* d_in, const int* in_sizes, int n_in,
                              void* d_out, int out_size) {
    const float* x   = (const float*)d_in[0];
    const float* wr  = (const float*)d_in[1];
    const float* w1  = (const float*)d_in[2];
    const float* w2  = (const float*)d_in[3];
    const float* ws1 = (const float*)d_in[4];
    const float* ws2 = (const float*)d_in[5];
    float* out = (float*)d_out;

    cudaFuncSetAttribute(gemm1_persist, cudaFuncAttributeMaxDynamicSharedMemorySize, SMEM_BYTES);
    cudaFuncSetAttribute(gemm2_persist, cudaFuncAttributeMaxDynamicSharedMemorySize, SMEM_BYTES);

    init_kernel<<<1, 32>>>();
    router_kernel<<<(NTOK * 32) / 256, 256>>>(x, wr);
    {
        long long n = 2LL * EDIM * FDIM * CDIM + 2LL * FSDIM * CDIM;
        cvt_weights_kernel<<<(int)((n / 4 + 255) / 256), 256>>>(w1, w2, ws1, ws2);
    }
    assign_kernel<<<(NTOK + 255) / 256, 256>>>();

    gemm1_persist<<<NPCTA, 256, SMEM_BYTES>>>();
    gemm2_persist<<<NPCTA, 256, SMEM_BYTES>>>(out);
    combine_kernel<<<(NTOK * CDIM / 4 + 255) / 256, 256>>>(out);
}

// round 16
// speedup vs baseline: 1.0326x; 1.0326x over previous
#include <cuda_runtime.h>
#include <cuda_fp16.h>
#include <cstdint>
#include <math.h>

// Problem constants
#define NTOK   4096
#define CDIM   1024
#define EDIM   8
#define FDIM   1024
#define FSDIM  2048
#define NPAIR  8192
#define NPCTA  148        // 1 CTA/SM (256x128 tile, 128 accum regs/thread)

// ---------------- scratch ----------------
__device__ __half g_xh[NTOK * CDIM];
__device__ __half g_w1h[EDIM * FDIM * CDIM];
__device__ __half g_w2h[EDIM * CDIM * FDIM];
__device__ __half g_ws1h[FSDIM * CDIM];
__device__ __half g_ws2h[CDIM * FSDIM];
__device__ __half g_midmoe[NPAIR * FDIM];
__device__ __half g_midsh[NTOK * FSDIM];
__device__ float  g_bin[NPAIR * CDIM];
__device__ int    g_counts[EDIM];
__device__ int    g_fill[EDIM];
__device__ int    g_off[EDIM];
__device__ int    g_te_off[EDIM + 1];   // 256-row-block tile prefix per expert
__device__ int    g_tok_e[NPAIR];
__device__ float  g_tok_w[NPAIR];
__device__ int    g_bin_tok[NPAIR];
__device__ int    g_tok_row[NPAIR];
__device__ int    g_ctr1, g_ctr2;

// ---------------- helpers ----------------
__device__ __forceinline__ uint32_t smem_u32(const void* p) {
    uint32_t a;
    asm("{ .reg .u64 t; cvta.to.shared.u64 t, %1; cvt.u32.u64 %0, t; }" : "=r"(a) : "l"(p));
    return a;
}
__device__ __forceinline__ void cp_async16(uint32_t dst, const void* src) {
    asm volatile("cp.async.ca.shared.global [%0], [%1], 16;" :: "r"(dst), "l"(src));
}
#define CP_COMMIT()   asm volatile("cp.async.commit_group;" ::: "memory")
#define CP_WAIT_1()   asm volatile("cp.async.wait_group 1;" ::: "memory")
#define CP_WAIT_ALL() asm volatile("cp.async.wait_group 0;" ::: "memory")

__device__ __forceinline__ void mma_f16(float* c, const uint32_t* a, const uint32_t* b) {
    asm volatile(
        "mma.sync.aligned.m16n8k16.row.col.f32.f16.f16.f32 "
        "{%0,%1,%2,%3}, {%4,%5,%6,%7}, {%8,%9}, {%0,%1,%2,%3};"
        : "+f"(c[0]), "+f"(c[1]), "+f"(c[2]), "+f"(c[3])
        : "r"(a[0]), "r"(a[1]), "r"(a[2]), "r"(a[3]), "r"(b[0]), "r"(b[1]));
}
__device__ __forceinline__ float sqrelu(float v) { return v > 0.f ? v * v : 0.f; }

// ---------------- GEMM tile core: BM=256, BN=128, BK=32 halfs, 3-stage cp.async ----------------
// SMEM stage: A fragment-direct [ks2][m16x16][reg4][lane32] = 4096 w; B [ks2][n8x16][reg2][lane32] = 2048 w
#define STW 6144
#define BW  4096
#define SMEM_BYTES (3 * STW * 4)    // 72 KB

// 8 warps: wm = wid>>1 (m-quadrant of 64); wn = wid&1 (n-half of 64). acc[4][8][4] = 128 regs.
__device__ __forceinline__ void run_tile(
    const __half* (&pa)[4], const __half* (&pb)[2], int nK,
    uint32_t* smw, uint32_t sm0, int tid, int wm, int wn, int lane,
    float (&acc)[4][8][4])
{
    uint32_t aoff[4], boff[2];
    #pragma unroll
    for (int j = 0; j < 4; j++) {
        int c = tid + j * 256;            // 0..1023: row = c>>2 (0..255), octet o = c&3
        int row = c >> 2, o = c & 3;
        int ks = o >> 1, ch = o & 1;
        aoff[j] = (uint32_t)(((ks * 16 + (row >> 4)) * 4 + (((row >> 3) & 1) + 2 * ch)) * 32 + (row & 7) * 4) * 4u;
    }
    #pragma unroll
    for (int j = 0; j < 2; j++) {
        int c = tid + j * 256;            // 0..511: row = c>>2 (0..127), octet o = c&3
        int row = c >> 2, o = c & 3;
        int ks = o >> 1, ch = o & 1;
        boff[j] = (uint32_t)(((ks * 16 + (row >> 3)) * 2 + ch) * 32 + (row & 7) * 4) * 4u;
    }

    auto issue = [&](int kt) {
        if (kt < nK) {
            const uint32_t sb = sm0 + (kt % 3) * (STW * 4);
            const int kadv = kt * 32;
            #pragma unroll
            for (int j = 0; j < 4; j++) cp_async16(sb + aoff[j], pa[j] + kadv);
            #pragma unroll
            for (int j = 0; j < 2; j++) cp_async16(sb + BW * 4 + boff[j], pb[j] + kadv);
        }
        CP_COMMIT();
    };

    issue(0); issue(1);

    for (int kt = 0; kt < nK; kt++) {
        CP_WAIT_1();
        __syncthreads();
        issue(kt + 2);
        const uint32_t sb = (kt % 3) * STW;
        #pragma unroll
        for (int s = 0; s < 2; s++) {
            uint32_t bf[8][2];
            #pragma unroll
            for (int j = 0; j < 8; j++) {
                uint32_t off = (uint32_t)(((s * 16 + wn * 8 + j) * 2) * 32 + lane);
                bf[j][0] = smw[sb + BW + off];  bf[j][1] = smw[sb + BW + off + 32];
            }
            #pragma unroll
            for (int i = 0; i < 4; i++) {
                uint32_t a[4];
                uint32_t off = (uint32_t)(((s * 16 + wm * 4 + i) * 4) * 32 + lane);
                #pragma unroll
                for (int r = 0; r < 4; r++) a[r] = smw[sb + off + r * 32];
                #pragma unroll
                for (int j = 0; j < 8; j++) mma_f16(acc[i][j], a, bf[j]);
            }
        }
    }
}

// ---------------- conversions ----------------
__global__ void cvt_weights_kernel(const float* __restrict__ w1, const float* __restrict__ w2,
                                   const float* __restrict__ ws1, const float* __restrict__ ws2) {
    const int WE = EDIM * FDIM * CDIM;
    const int SE = FSDIM * CDIM;
    long long i = (long long)(blockIdx.x * blockDim.x + threadIdx.x) * 4;
    const float* src; __half* dst; long long off;
    if      (i < WE)               { src = w1;  dst = g_w1h;  off = i; }
    else if (i < 2LL * WE)         { src = w2;  dst = g_w2h;  off = i - WE; }
    else if (i < 2LL * WE + SE)    { src = ws1; dst = g_ws1h; off = i - 2LL * WE; }
    else if (i < 2LL * WE + 2*SE)  { src = ws2; dst = g_ws2h; off = i - 2LL * WE - SE; }
    else return;
    float4 v = *(const float4*)(src + off);
    ushort4 hh;
    hh.x = __half_as_ushort(__float2half_rn(v.x));
    hh.y = __half_as_ushort(__float2half_rn(v.y));
    hh.z = __half_as_ushort(__float2half_rn(v.z));
    hh.w = __half_as_ushort(__float2half_rn(v.w));
    *(ushort4*)(dst + off) = hh;
}

// ---------------- routing ----------------
__global__ void init_kernel() {
    int i = threadIdx.x;
    if (i < EDIM) { g_counts[i] = 0; g_fill[i] = 0; }
    if (i == 0) { g_ctr1 = 0; g_ctr2 = 0; }
}

__global__ void router_kernel(const float* __restrict__ x, const float* __restrict__ wr) {
    int gw = (blockIdx.x * blockDim.x + threadIdx.x) >> 5;
    int lane = threadIdx.x & 31;
    if (gw >= NTOK) return;
    const float* xr = x + (size_t)gw * CDIM;
    __half* xhr = g_xh + (size_t)gw * CDIM;
    float acc[EDIM] = {0.f, 0.f, 0.f, 0.f, 0.f, 0.f, 0.f, 0.f};
    for (int c = lane; c < CDIM; c += 32) {
        float xv = xr[c];
        xhr[c] = __float2half_rn(xv);
        #pragma unroll
        for (int e = 0; e < EDIM; e++) acc[e] = fmaf(xv, wr[e * CDIM + c], acc[e]);
    }
    #pragma unroll
    for (int e = 0; e < EDIM; e++) {
        #pragma unroll
        for (int o = 16; o; o >>= 1) acc[e] += __shfl_xor_sync(0xffffffffu, acc[e], o);
    }
    if (lane == 0) {
        float m = acc[0];
        #pragma unroll
        for (int e = 1; e < EDIM; e++) m = fmaxf(m, acc[e]);
        float p[EDIM];
        #pragma unroll
        for (int e = 0; e < EDIM; e++) p[e] = expf(acc[e] - m);
        int i0 = 0; float p0 = p[0];
        #pragma unroll
        for (int e = 1; e < EDIM; e++) if (p[e] > p0) { p0 = p[e]; i0 = e; }
        int i1 = -1; float p1 = -1.f;
        #pragma unroll
        for (int e = 0; e < EDIM; e++) if (e != i0 && p[e] > p1) { p1 = p[e]; i1 = e; }
        float s = p0 + p1;
        g_tok_e[2 * gw + 0] = i0;  g_tok_w[2 * gw + 0] = p0 / s;
        g_tok_e[2 * gw + 1] = i1;  g_tok_w[2 * gw + 1] = p1 / s;
        atomicAdd(&g_counts[i0], 1);
        atomicAdd(&g_counts[i1], 1);
    }
}

// assign: threads compute the 8-element offset prefix locally (no offsets_kernel);
// thread 0 publishes g_off / g_te_off for the GEMM kernels (they launch strictly after).
__global__ void assign_kernel() {
    int t = blockIdx.x * blockDim.x + threadIdx.x;
    if (t >= NTOK) return;
    int cnt[EDIM], off[EDIM];
    int s = 0;
    #pragma unroll
    for (int e = 0; e < EDIM; e++) { cnt[e] = g_counts[e]; off[e] = s; s += cnt[e]; }
    if (t == 0) {
        int ts = 0;
        g_te_off[0] = 0;
        #pragma unroll
        for (int e = 0; e < EDIM; e++) {
            g_off[e] = off[e];
            ts += ((cnt[e] + 255) >> 8) * 8;
            g_te_off[e + 1] = ts;
        }
    }
    #pragma unroll
    for (int k = 0; k < 2; k++) {
        int e = g_tok_e[2 * t + k];
        int slot = atomicAdd(&g_fill[e], 1);
        int r = off[e] + slot;
        g_bin_tok[r] = t;
        g_tok_row[2 * t + k] = r;
    }
}

// ---------------- GEMM1 persistent: tiles [0,256) s1 (16m x 16n), rest moe1 ----------------
__global__ __launch_bounds__(256, 1) void gemm1_persist() {
    extern __shared__ uint32_t smw[];
    const uint32_t sm0 = smem_u32(smw);
    __shared__ int s_t;
    const int tid = threadIdx.x, wid = tid >> 5, lane = tid & 31;
    const int wm = wid >> 1, wn = wid & 1;
    const int total = 256 + g_te_off[EDIM];

    for (;;) {
        __syncthreads();
        if (tid == 0) s_t = atomicAdd(&g_ctr1, 1);
        __syncthreads();
        const int t = s_t;
        if (t >= total) { CP_WAIT_ALL(); break; }

        int m0, n0, Mtot, rowbase, N;
        bool moe;
        const __half* Bp; __half* Out;
        if (t < 256) {
            moe = false; n0 = (t & 15) * 128; m0 = (t >> 4) * 256;
            Mtot = NTOK; rowbase = 0; N = FSDIM; Bp = g_ws1h; Out = g_midsh;
        } else {
            moe = true;
            int tt = t - 256, e = 0;
            while (e < EDIM - 1 && tt >= g_te_off[e + 1]) e++;
            int local = tt - g_te_off[e];
            n0 = (local & 7) * 128; m0 = (local >> 3) * 256;
            Mtot = g_counts[e]; rowbase = g_off[e]; N = FDIM;
            Bp = g_w1h + (size_t)e * FDIM * CDIM; Out = g_midmoe;
        }

        const __half* pa[4]; const __half* pb[2];
        #pragma unroll
        for (int j = 0; j < 4; j++) {
            int c = tid + j * 256;
            int row = c >> 2, o = c & 3;
            int am = m0 + row;
            size_t arow;
            if (moe) arow = (size_t)g_bin_tok[rowbase + (am < Mtot ? am : 0)];
            else     arow = (size_t)(am < Mtot ? am : m0);
            pa[j] = g_xh + arow * CDIM + o * 8;
        }
        #pragma unroll
        for (int j = 0; j < 2; j++) {
            int c = tid + j * 256;
            int row = c >> 2, o = c & 3;
            pb[j] = Bp + (size_t)(n0 + row) * CDIM + o * 8;
        }

        float acc[4][8][4];
        #pragma unroll
        for (int i = 0; i < 4; i++)
            #pragma unroll
            for (int j = 0; j < 8; j++)
                #pragma unroll
                for (int r = 0; r < 4; r++) acc[i][j][r] = 0.f;

        run_tile(pa, pb, CDIM / 32, smw, sm0, tid, wm, wn, lane, acc);

        #pragma unroll
        for (int i = 0; i < 4; i++) {
            const int rbase = m0 + wm * 64 + i * 16 + (lane >> 2);
            #pragma unroll
            for (int half = 0; half < 2; half++) {
                const int mrow = rbase + half * 8;
                if (mrow >= Mtot) continue;
                #pragma unroll
                for (int j = 0; j < 8; j++) {
                    const int col = n0 + wn * 64 + j * 8 + (lane & 3) * 2;
                    __half2 h2 = __floats2half2_rn(sqrelu(acc[i][j][half * 2 + 0]),
                                                   sqrelu(acc[i][j][half * 2 + 1]));
                    *(__half2*)(Out + (size_t)(rowbase + mrow) * N + col) = h2;
                }
            }
        }
    }
}

// ---------------- GEMM2 persistent: tiles [0,128) s2 (16m x 8n), rest moe2 -> bin ----------------
__global__ __launch_bounds__(256, 1) void gemm2_persist(float* __restrict__ OutF) {
    extern __shared__ uint32_t smw[];
    const uint32_t sm0 = smem_u32(smw);
    __shared__ int s_t;
    const int tid = threadIdx.x, wid = tid >> 5, lane = tid & 31;
    const int wm = wid >> 1, wn = wid & 1;
    const int total = 128 + g_te_off[EDIM];

    for (;;) {
        __syncthreads();
        if (tid == 0) s_t = atomicAdd(&g_ctr2, 1);
        __syncthreads();
        const int t = s_t;
        if (t >= total) { CP_WAIT_ALL(); break; }

        int m0, n0, Mtot, rowbase, Kd;
        const __half* Ap; const __half* Bp; float* dst;
        if (t < 128) {
            n0 = (t & 7) * 128; m0 = (t >> 3) * 256;
            Mtot = NTOK; rowbase = 0; Kd = FSDIM;
            Ap = g_midsh; Bp = g_ws2h; dst = OutF;
        } else {
            int tt = t - 128, e = 0;
            while (e < EDIM - 1 && tt >= g_te_off[e + 1]) e++;
            int local = tt - g_te_off[e];
            n0 = (local & 7) * 128; m0 = (local >> 3) * 256;
            Mtot = g_counts[e]; rowbase = g_off[e]; Kd = FDIM;
            Ap = g_midmoe; Bp = g_w2h + (size_t)e * CDIM * FDIM; dst = g_bin;
        }

        const __half* pa[4]; const __half* pb[2];
        #pragma unroll
        for (int j = 0; j < 4; j++) {
            int c = tid + j * 256;
            int row = c >> 2, o = c & 3;
            int am = m0 + row;
            size_t arow = (size_t)(rowbase + (am < Mtot ? am : m0));
            pa[j] = Ap + arow * Kd + o * 8;
        }
        #pragma unroll
        for (int j = 0; j < 2; j++) {
            int c = tid + j * 256;
            int row = c >> 2, o = c & 3;
            pb[j] = Bp + (size_t)(n0 + row) * Kd + o * 8;
        }

        float acc[4][8][4];
        #pragma unroll
        for (int i = 0; i < 4; i++)
            #pragma unroll
            for (int j = 0; j < 8; j++)
                #pragma unroll
                for (int r = 0; r < 4; r++) acc[i][j][r] = 0.f;

        run_tile(pa, pb, Kd / 32, smw, sm0, tid, wm, wn, lane, acc);

        #pragma unroll
        for (int i = 0; i < 4; i++) {
            const int rbase = m0 + wm * 64 + i * 16 + (lane >> 2);
            #pragma unroll
            for (int half = 0; half < 2; half++) {
                const int mrow = rbase + half * 8;
                if (mrow >= Mtot) continue;
                #pragma unroll
                for (int j = 0; j < 8; j++) {
                    const int col = n0 + wn * 64 + j * 8 + (lane & 3) * 2;
                    float2 o2;
                    o2.x = acc[i][j][half * 2 + 0];
                    o2.y = acc[i][j][half * 2 + 1];
                    *(float2*)(dst + (size_t)(rowbase + mrow) * CDIM + col) = o2;
                }
            }
        }
    }
}

// ---------------- combine: out[t] += w0*bin[r0] + w1*bin[r1] ----------------
__global__ void combine_kernel(float* __restrict__ out) {
    int idx = (blockIdx.x * blockDim.x + threadIdx.x) * 4;
    if (idx >= NTOK * CDIM) return;
    int t = idx >> 10;
    int c = idx & 1023;
    float w0 = g_tok_w[2 * t], w1 = g_tok_w[2 * t + 1];
    size_t r0 = (size_t)g_tok_row[2 * t], r1 = (size_t)g_tok_row[2 * t + 1];
    float4 o  = *(float4*)(out + idx);
    float4 b0 = *(const float4*)(g_bin + r0 * CDIM + c);
    float4 b1 = *(const float4*)(g_bin + r1 * CDIM + c);
    o.x += w0 * b0.x + w1 * b1.x;
    o.y += w0 * b0.y + w1 * b1.y;
    o.z += w0 * b0.z + w1 * b1.z;
    o.w += w0 * b0.w + w1 * b1.w;
    *(float4*)(out + idx) = o;
}

// ---------------- launch ----------------
extern "C" void kernel_launch(void* const* d_in, const int* in_sizes, int n_in,
                              void* d_out, int out_size) {
    const float* x   = (const float*)d_in[0];
    const float* wr  = (const float*)d_in[1];
    const float* w1  = (const float*)d_in[2];
    const float* w2  = (const float*)d_in[3];
    const float* ws1 = (const float*)d_in[4];
    const float* ws2 = (const float*)d_in[5];
    float* out = (float*)d_out;

    cudaFuncSetAttribute(gemm1_persist, cudaFuncAttributeMaxDynamicSharedMemorySize, SMEM_BYTES);
    cudaFuncSetAttribute(gemm2_persist, cudaFuncAttributeMaxDynamicSharedMemorySize, SMEM_BYTES);

    init_kernel<<<1, 32>>>();
    router_kernel<<<(NTOK * 32) / 256, 256>>>(x, wr);
    {
        long long n = 2LL * EDIM * FDIM * CDIM + 2LL * FSDIM * CDIM;
        cvt_weights_kernel<<<(int)((n / 4 + 255) / 256), 256>>>(w1, w2, ws1, ws2);
    }
    assign_kernel<<<(NTOK + 255) / 256, 256>>>();

    gemm1_persist<<<NPCTA, 256, SMEM_BYTES>>>();
    gemm2_persist<<<NPCTA, 256, SMEM_BYTES>>>(out);
    combine_kernel<<<(NTOK * CDIM / 4 + 255) / 256, 256>>>(out);
}